// round 14
// baseline (speedup 1.0000x reference)
#include <cuda_runtime.h>

// SpikingAttentionJAX — ONE kernel, ZERO grid sync (R13 + chain surgery).
// LIF scan collapses to per-token occurrence counts (per-entry updates
// commute; entry t's final state depends only on count n_t and v0[t]).
//
// 125 blocks x 1024 threads; block b owns vocab slice [1024b, 1024b+1024).
// Each block histograms the whole 8192-token stream (8 tokens/thread, two
// independent int4 loads, L2-broadcast) into shared memory; v0 prefetched
// before the scan. Then LIF replay, gain store (0.6 spiked / 1.0).
// Warp top-5: REDUX.UMAX + ballot/ffs (lane order == index order, so the
// lowest set lane IS the JAX lower-index tie-break winner; its index is
// affine in lane — no shuffle needed). Warp0 merges 160 packed keys ->
// block top-5 -> g_cand. Done-counter uses a single acq_rel atomic (fused
// release of this block's writes + acquire of everyone's g_cand — replaces
// two full __threadfence drains). LAST arriving block finalizes: 625 keys,
// 1/thread, per-warp REDUX top-5, ONE barrier, warp0 register merge,
// 5 winner stores (1.5). Packed monotone key: (ordered_float(v)<<32)|~idx.

static constexpr float DECAY     = 0.7f;
static constexpr float THETA     = 1.0f;
static constexpr float GAIN_UP   = 1.5f;
static constexpr float GAIN_DOWN = 0.6f;
static constexpr int   KW   = 5;
static constexpr int   NT   = 1024;
static constexpr int   NW   = NT / 32;       // 32 warps
static constexpr int   MAXB = 256;           // >= grid (125)

__device__ unsigned long long g_cand[MAXB * KW];
__device__ unsigned g_done = 0;              // monotonic across graph replays

__device__ __forceinline__ unsigned ordered_bits(float f) {
    unsigned u = __float_as_uint(f);
    return (u & 0x80000000u) ? ~u : (u | 0x80000000u);   // >0 for finite f
}

__global__ __launch_bounds__(NT)
void k_main(const int* __restrict__ tok, const float* __restrict__ v0,
            float* __restrict__ out, int seq, int vocab, int nblocks) {
    const int tid  = threadIdx.x;
    const int lane = tid & 31;
    const int wid  = tid >> 5;
    const int base = blockIdx.x * NT;            // this block's vocab slice
    const int i    = base + tid;                 // this thread's vocab entry
    const bool live = (i < vocab);

    __shared__ int                sh_cnt[NT];
    __shared__ unsigned long long s_m[NW * KW];  // 160 packed candidates
    __shared__ unsigned           s_last;

    // ---- prefetch v0 early (independent of histogram; hides DRAM latency) ----
    float vpre = live ? __ldg(&v0[i]) : 0.0f;

    sh_cnt[tid] = 0;
    __syncthreads();

    // ---- histogram whole token stream for this slice (2 indep int4/thread) ----
    const int4* tok4 = reinterpret_cast<const int4*>(tok);
    const int   n4   = seq >> 2;                 // 2048
    int4 ta, tb;
    const bool hasA = (tid < n4), hasB = (tid + NT < n4);
    if (hasA) ta = __ldg(&tok4[tid]);
    if (hasB) tb = __ldg(&tok4[tid + NT]);
    if (hasA) {
        int t;
        t = ta.x; t = t < 0 ? 0 : (t >= vocab ? vocab - 1 : t);
        if ((unsigned)(t - base) < (unsigned)NT) atomicAdd(&sh_cnt[t - base], 1);
        t = ta.y; t = t < 0 ? 0 : (t >= vocab ? vocab - 1 : t);
        if ((unsigned)(t - base) < (unsigned)NT) atomicAdd(&sh_cnt[t - base], 1);
        t = ta.z; t = t < 0 ? 0 : (t >= vocab ? vocab - 1 : t);
        if ((unsigned)(t - base) < (unsigned)NT) atomicAdd(&sh_cnt[t - base], 1);
        t = ta.w; t = t < 0 ? 0 : (t >= vocab ? vocab - 1 : t);
        if ((unsigned)(t - base) < (unsigned)NT) atomicAdd(&sh_cnt[t - base], 1);
    }
    if (hasB) {
        int t;
        t = tb.x; t = t < 0 ? 0 : (t >= vocab ? vocab - 1 : t);
        if ((unsigned)(t - base) < (unsigned)NT) atomicAdd(&sh_cnt[t - base], 1);
        t = tb.y; t = t < 0 ? 0 : (t >= vocab ? vocab - 1 : t);
        if ((unsigned)(t - base) < (unsigned)NT) atomicAdd(&sh_cnt[t - base], 1);
        t = tb.z; t = t < 0 ? 0 : (t >= vocab ? vocab - 1 : t);
        if ((unsigned)(t - base) < (unsigned)NT) atomicAdd(&sh_cnt[t - base], 1);
        t = tb.w; t = t < 0 ? 0 : (t >= vocab ? vocab - 1 : t);
        if ((unsigned)(t - base) < (unsigned)NT) atomicAdd(&sh_cnt[t - base], 1);
    }
    // generic tails (inactive for seq=8192, NT=1024)
    for (int c = 2 * NT + tid; c < n4; c += NT) {
        int4 t4 = __ldg(&tok4[c]);
        int t;
        t = t4.x; t = t < 0 ? 0 : (t >= vocab ? vocab - 1 : t);
        if ((unsigned)(t - base) < (unsigned)NT) atomicAdd(&sh_cnt[t - base], 1);
        t = t4.y; t = t < 0 ? 0 : (t >= vocab ? vocab - 1 : t);
        if ((unsigned)(t - base) < (unsigned)NT) atomicAdd(&sh_cnt[t - base], 1);
        t = t4.z; t = t < 0 ? 0 : (t >= vocab ? vocab - 1 : t);
        if ((unsigned)(t - base) < (unsigned)NT) atomicAdd(&sh_cnt[t - base], 1);
        t = t4.w; t = t < 0 ? 0 : (t >= vocab ? vocab - 1 : t);
        if ((unsigned)(t - base) < (unsigned)NT) atomicAdd(&sh_cnt[t - base], 1);
    }
    for (int c = (n4 << 2) + tid; c < seq; c += NT) {
        int t = __ldg(&tok[c]);
        t = t < 0 ? 0 : (t >= vocab ? vocab - 1 : t);
        if ((unsigned)(t - base) < (unsigned)NT) atomicAdd(&sh_cnt[t - base], 1);
    }
    __syncthreads();

    // ---- LIF replay + gains ----
    unsigned uval = 0u;                          // 0 = invalid/popped sentinel
    if (live) {
        int   cnt = sh_cnt[tid];
        float v   = vpre;
        int s = 0;
        for (int it = 0; it < cnt; it++) {
            float vn = DECAY * v + 1.0f;
            if (vn >= THETA) { v = vn - THETA; s++; }
            else             { v = vn; }
        }
        out[i] = (s > 0) ? GAIN_DOWN : 1.0f;
        uval = ordered_bits(v);
    }

    // ---- warp top-5: REDUX.UMAX + ballot/ffs (lane order == index order) ----
    const unsigned warp_ibase = (unsigned)(base + (wid << 5));  // index of lane 0
    #pragma unroll
    for (int r = 0; r < KW; r++) {
        unsigned m    = __reduce_max_sync(0xffffffffu, uval);
        unsigned ball = __ballot_sync(0xffffffffu, uval == m);
        int      src  = __ffs(ball) - 1;         // lowest lane = lowest index
        if (lane == 0)
            s_m[wid * KW + r] = ((unsigned long long)m << 32) |
                (unsigned long long)(0xffffffffu - (warp_ibase + (unsigned)src));
        if (lane == src) uval = 0u;              // pop exactly the winner
    }
    __syncthreads();

    // ---- warp 0: merge 160 packed keys -> block top-5 -> g_cand ----
    if (wid == 0) {
        unsigned long long a[KW];                // 5 packed slots/lane
        #pragma unroll
        for (int s = 0; s < KW; s++) a[s] = s_m[s * 32 + lane];
        #pragma unroll
        for (int r = 0; r < KW; r++) {
            unsigned long long b = a[0];
            #pragma unroll
            for (int s = 1; s < KW; s++) if (a[s] > b) b = a[s];   // monotone key
            unsigned bh = (unsigned)(b >> 32);
            unsigned wm = __reduce_max_sync(0xffffffffu, bh);
            unsigned bl = (bh == wm) ? (unsigned)(b & 0xffffffffull) : 0u;
            unsigned wl = __reduce_max_sync(0xffffffffu, bl);      // max ~idx
            unsigned long long win = ((unsigned long long)wm << 32) | wl;
            if (lane == 0) g_cand[blockIdx.x * KW + r] = win;
            #pragma unroll
            for (int s = 0; s < KW; s++) if (a[s] == win) a[s] = 0ull;
        }
    }

    // ---- done-counter: single acq_rel atomic (fused release + acquire) ----
    if (tid == 0) {
        unsigned old;
        asm volatile("atom.add.acq_rel.gpu.global.u32 %0, [%1], %2;"
                     : "=r"(old)
                     : "l"(&g_done), "r"(1u)
                     : "memory");
        s_last = (((old + 1) % (unsigned)nblocks) == 0u) ? 1u : 0u;
    }
    __syncthreads();
    if (!s_last) return;

    // ---- finalizer: 625 keys, 1/thread -> per-warp REDUX top-5 -> 1 BAR ----
    const int ncand = nblocks * KW;              // 625 <= 1024
    unsigned long long key = (tid < ncand) ? g_cand[tid] : 0ull;
    unsigned hv = (unsigned)(key >> 32);
    unsigned lo = (unsigned)(key & 0xffffffffull);

    #pragma unroll
    for (int r = 0; r < KW; r++) {
        unsigned wm = __reduce_max_sync(0xffffffffu, hv);
        unsigned cl = (hv == wm) ? lo : 0u;
        unsigned wl = __reduce_max_sync(0xffffffffu, cl);  // max ~idx = min idx
        if (lane == 0) s_m[wid * KW + r] = ((unsigned long long)wm << 32) | wl;
        if (hv == wm && lo == wl) { hv = 0u; lo = 0u; }    // pop (keys unique)
    }
    __syncthreads();                             // single barrier in finalize

    if (wid == 0) {
        unsigned long long a[KW];                // 5 slots/lane over 160 keys
        #pragma unroll
        for (int s = 0; s < KW; s++) a[s] = s_m[s * 32 + lane];
        #pragma unroll
        for (int r = 0; r < KW; r++) {
            unsigned long long b = a[0];
            #pragma unroll
            for (int s = 1; s < KW; s++) if (a[s] > b) b = a[s];
            unsigned bh = (unsigned)(b >> 32);
            unsigned wm = __reduce_max_sync(0xffffffffu, bh);
            unsigned bl = (bh == wm) ? (unsigned)(b & 0xffffffffull) : 0u;
            unsigned wl = __reduce_max_sync(0xffffffffu, bl);
            if (lane == 0 && wm != 0u)
                out[0xffffffffu - wl] = GAIN_UP; // >=5 unique real keys exist
            unsigned long long win = ((unsigned long long)wm << 32) | wl;
            #pragma unroll
            for (int s = 0; s < KW; s++) if (a[s] == win) a[s] = 0ull;
        }
    }
}

// ---------------------------------------------------------------- launch
extern "C" void kernel_launch(void* const* d_in, const int* in_sizes, int n_in,
                              void* d_out, int out_size) {
    const int*   tok = (const int*)d_in[0];
    const float* v0  = (const float*)d_in[1];
    const int seq   = in_sizes[0];
    const int vocab = in_sizes[1];
    float* out = (float*)d_out;

    int gblocks = (vocab + NT - 1) / NT;         // 125 for vocab=128000
    k_main<<<gblocks, NT>>>(tok, v0, out, seq, vocab, gblocks);
}